// round 14
// baseline (speedup 1.0000x reference)
#include <cuda_runtime.h>
#include <cuda_bf16.h>
#include <cstdint>

// BasicLSTM via mma.sync (HMMA bf16, 3-term fp32-split emulation).
// SEQ=512, BATCH=64, HID=1024, LAYERS=2.
// R14: 256 CTAs x 256 thr, 2 CTAs/SM (occupancy-based LDS/MMA overlap).
// lay(2) x M-tile(32) x split-K(4, K=512). 2-stage cp.async, R7-style loop.
// 8 warps = 8 (m,n) positions, all 4 kk per warp -> no kk-reduction.

#define SEQ    512
#define BATCH  64
#define HID    1024
#define KTOT   2048
#define NOUT   4096
#define BH     (BATCH * HID)        // 65536
#define NBLK   256
#define NTHR   256
#define GTH    (NBLK * NTHR)
#define KSL    512                  // K per slice (4 slices per layer)
#define CHK    64                   // K per chunk
#define NCHK   (KSL / CHK)          // 8
#define STGB   49152                // Ahi16K | Alo16K | Bhi8K | Blo8K
#define NSTG   2
#define DSMEM  (NSTG * STGB)        // 98304

// ---------------- device globals (no allocs) ----------------
__device__ __align__(128) __nv_bfloat16 g_xhi[(size_t)SEQ * HID * 64];
__device__ __align__(128) __nv_bfloat16 g_xlo[(size_t)SEQ * HID * 64];
__device__ __align__(128) __nv_bfloat16 g_wthi[(size_t)2 * NOUT * KTOT]; // [l][p][k]
__device__ __align__(128) __nv_bfloat16 g_wtlo[(size_t)2 * NOUT * KTOT];
__device__ __align__(128) __nv_bfloat16 g_hhi[2 * BH];    // [l][u][b]
__device__ __align__(128) __nv_bfloat16 g_hlo[2 * BH];
__device__ __align__(128) float g_partial[(size_t)8 * NOUT * 64]; // [lay*4+ks][p][b]
__device__ __align__(128) float g_c[2 * BH];              // [l][u][b]
__device__ __align__(128) float g_hf[2 * BH];             // [l][u][b]
__device__ unsigned g_bar_arrive;
__device__ unsigned g_bar_gen;

// ---------------- PTX helpers ----------------
__device__ __forceinline__ uint32_t smem_u32(const void* p) {
    uint32_t a;
    asm("{ .reg .u64 t; cvta.to.shared.u64 t, %1; cvt.u32.u64 %0, t; }"
        : "=r"(a) : "l"(p));
    return a;
}
__device__ __forceinline__ void cpa16(uint32_t s, const void* g) {
    asm volatile("cp.async.cg.shared.global [%0], [%1], 16;" :: "r"(s), "l"(g));
}
__device__ __forceinline__ void cpa_commit() {
    asm volatile("cp.async.commit_group;" ::: "memory");
}
__device__ __forceinline__ void cpa_wait1() {
    asm volatile("cp.async.wait_group 1;" ::: "memory");
}
__device__ __forceinline__ void cpa_wait0() {
    asm volatile("cp.async.wait_group 0;" ::: "memory");
}
__device__ __forceinline__ void ldsm4(uint32_t a, uint32_t* r) {
    asm volatile("ldmatrix.sync.aligned.m8n8.x4.shared.b16 {%0,%1,%2,%3}, [%4];"
                 : "=r"(r[0]), "=r"(r[1]), "=r"(r[2]), "=r"(r[3]) : "r"(a));
}
__device__ __forceinline__ void ldsm4t(uint32_t a, uint32_t* r) {
    asm volatile("ldmatrix.sync.aligned.m8n8.x4.trans.shared.b16 {%0,%1,%2,%3}, [%4];"
                 : "=r"(r[0]), "=r"(r[1]), "=r"(r[2]), "=r"(r[3]) : "r"(a));
}
__device__ __forceinline__ void mma16816(float* c, const uint32_t* a,
                                         uint32_t b0, uint32_t b1) {
    asm volatile("mma.sync.aligned.m16n8k16.row.col.f32.bf16.bf16.f32 "
                 "{%0,%1,%2,%3}, {%4,%5,%6,%7}, {%8,%9}, {%0,%1,%2,%3};"
                 : "+f"(c[0]), "+f"(c[1]), "+f"(c[2]), "+f"(c[3])
                 : "r"(a[0]), "r"(a[1]), "r"(a[2]), "r"(a[3]), "r"(b0), "r"(b1));
}
__device__ __forceinline__ float sigmoidf_(float x) { return 1.0f / (1.0f + expf(-x)); }
__device__ __forceinline__ void split1(float v, __nv_bfloat16& h, __nv_bfloat16& l) {
    h = __float2bfloat16_rn(v);
    l = __float2bfloat16_rn(v - __bfloat162float(h));
}
__device__ __forceinline__ uint32_t swz(uint32_t off) {
    return off ^ ((off >> 3) & 0x70);
}

// ---------------- grid barrier (all 256 blocks resident: 2/SM) -----------
__device__ __forceinline__ void grid_barrier() {
    __syncthreads();
    if (threadIdx.x == 0) {
        __threadfence();
        unsigned gen = *((volatile unsigned*)&g_bar_gen);
        if (atomicAdd(&g_bar_arrive, 1u) == NBLK - 1) {
            g_bar_arrive = 0;
            __threadfence();
            atomicAdd(&g_bar_gen, 1u);
        } else {
            while (*((volatile unsigned*)&g_bar_gen) == gen) { __nanosleep(20); }
        }
        __threadfence();
    }
    __syncthreads();
}

// ---------------- persistent kernel ----------------
__global__ void __launch_bounds__(NTHR, 2)
lstm_hmma(const float* __restrict__ input,   // [512,64,1024]
          const float* __restrict__ h0,      // [2,64,1024]
          const float* __restrict__ c0,      // [2,64,1024]
          const float* __restrict__ W,       // [2,2048,4096]
          const float* __restrict__ bias,    // [2,4096]
          float* __restrict__ out)
{
    extern __shared__ __align__(1024) char dsm[];
    const uint32_t sbase = smem_u32(dsm);

    __shared__ float s_tr[32][33];
    __shared__ float s_hn[8][64];

    const int tid  = threadIdx.x;
    const int wid  = tid >> 5;
    const int lane = tid & 31;
    const int bid  = blockIdx.x;
    const int gid  = bid * NTHR + tid;
    const int lay  = bid >> 7;        // 0: layer0@s, 1: layer1@(s-1)
    const int cg   = (bid >> 2) & 31; // M tile: rows [cg*128, +128)
    const int ks   = bid & 3;         // K slice: [ks*512, +512)
    const int pgrp = bid & 255 ? (lay * 4 + ks) : 0; // = lay*4+ks
    const int m0   = cg * 128;
    // cell ownership: layer cl = bid&1, units [ (bid>>1)*8, +8 )
    const int ccl  = bid & 1;
    const int u0   = (bid >> 1) * 8;

    // warp mapping: 8 warps -> 4 mq x 2 nh m32n32 positions, all 4 kk each
    const int mq = wid >> 1;          // m offset mq*32
    const int nh = wid & 1;           // n offset nh*32

    // ======== phase 0a: x transpose [t][b][u] -> [t][u][b] + bf16 split ====
    for (int tile = bid; tile < SEQ * 64; tile += NBLK) {
        const int t  = tile >> 6;
        const int ut = (tile >> 1) & 31;
        const int bt = tile & 1;
        const int ub = ut * 32, bb = bt * 32;
#pragma unroll
        for (int it = 0; it < 4; it++) {
            int r = (tid >> 5) + it * 8, c = lane;
            s_tr[r][c] = input[((size_t)t * 64 + bb + r) * HID + ub + c];
        }
        __syncthreads();
#pragma unroll
        for (int it = 0; it < 4; it++) {
            int i = (tid >> 5) + it * 8, j = lane;
            __nv_bfloat16 hv, lv;
            split1(s_tr[j][i], hv, lv);
            size_t dst = ((size_t)t * HID + ub + i) * 64 + bb + j;
            g_xhi[dst] = hv;
            g_xlo[dst] = lv;
        }
        __syncthreads();
    }
    // ======== phase 0b: W transpose + gate-permute + split ========
    for (int tile = bid; tile < 2 * 64 * 128; tile += NBLK) {
        const int l  = tile >> 13;
        const int kt = (tile & 8191) >> 7;
        const int nt = tile & 127;
        const int k0 = kt * 32, n0 = nt * 32;
#pragma unroll
        for (int r = 0; r < 4; r++) {
            int kk = (tid >> 5) + r * 8;
            s_tr[kk][lane] = W[((size_t)l * KTOT + k0 + kk) * NOUT + n0 + lane];
        }
        __syncthreads();
#pragma unroll
        for (int r = 0; r < 4; r++) {
            int j = (tid >> 5) + r * 8;
            int n = n0 + j;
            int p = ((n & 1023) << 2) | (n >> 10);
            __nv_bfloat16 hv, lv;
            split1(s_tr[lane][j], hv, lv);
            size_t dst = ((size_t)l * NOUT + p) * KTOT + k0 + lane;
            g_wthi[dst] = hv;
            g_wtlo[dst] = lv;
        }
        __syncthreads();
    }
    // ======== phase 0c: seed h (transposed, split) and c (transposed) =====
    for (int tile = bid; tile < 256; tile += NBLK) {
        const int kind = tile >> 7;
        const int rest = tile & 127;
        const int l  = rest >> 6;
        const int ut = (rest >> 1) & 31;
        const int bt = rest & 1;
        const int ub = ut * 32, bb = bt * 32;
        const float* src = (kind == 0) ? h0 : c0;
#pragma unroll
        for (int it = 0; it < 4; it++) {
            int r = (tid >> 5) + it * 8, c = lane;
            s_tr[r][c] = src[((size_t)l * 64 + bb + r) * HID + ub + c];
        }
        __syncthreads();
#pragma unroll
        for (int it = 0; it < 4; it++) {
            int i = (tid >> 5) + it * 8, j = lane;
            float v = s_tr[j][i];
            if (kind == 0) {
                __nv_bfloat16 hv, lv;
                split1(v, hv, lv);
                size_t dst = (size_t)l * BH + (size_t)(ub + i) * 64 + bb + j;
                g_hhi[dst] = hv;
                g_hlo[dst] = lv;
            } else {
                g_c[(size_t)l * BH + (size_t)(ub + i) * 64 + bb + j] = v;
            }
        }
        __syncthreads();
    }
    grid_barrier();

    // ---- lane-constant ldmatrix row bases + swizzle XORs ----
    const int q  = lane >> 3, r8 = lane & 7;
    const int rowA = mq * 32 + r8 + (q & 1) * 8;
    const uint32_t baseA = (uint32_t)rowA * 128;
    const uint32_t xorA  = (uint32_t)(rowA & 7) * 16;
    const int rowB = (q & 1) * 8 + r8;
    const uint32_t baseB = (uint32_t)rowB * 128;
    const uint32_t xorB  = (uint32_t)(rowB & 7) * 16;
    const uint32_t colq  = (uint32_t)(q >> 1) * 16;

    // ---- hoisted cp.async addressing ----
    const int irow32 = tid >> 3;               // 0..31
    const int ic8    = (tid & 7) * 8;
    uint32_t offW[4], offB[2];
#pragma unroll
    for (int it = 0; it < 4; it++)
        offW[it] = swz((uint32_t)(irow32 + it * 32) * 128 + (tid & 7) * 16);
#pragma unroll
    for (int it = 0; it < 2; it++)
        offB[it] = swz((uint32_t)(irow32 + it * 32) * 128 + (tid & 7) * 16);

    // W per-thread base pointers (row block it adds 32*KTOT)
    const __nv_bfloat16* WhP = g_wthi + ((size_t)lay * NOUT + m0 + irow32) * KTOT
                             + ks * KSL + ic8;
    const __nv_bfloat16* WoP = g_wtlo + ((size_t)lay * NOUT + m0 + irow32) * KTOT
                             + ks * KSL + ic8;

    // ======== main recurrence: 513 super-steps ========
    for (int s = 0; s <= SEQ; s++) {
        const bool do_l0 = (s < SEQ);
        const bool do_l1 = (s >= 1);
        const bool active = (lay == 0) ? do_l0 : do_l1;

        if (active) {
            // ---- B operand selection ----
            const __nv_bfloat16 *Bh, *Bl;
            int koff;
            if (lay == 0) {
                if (ks < 2) { Bh = g_xhi + (size_t)s * BH; Bl = g_xlo + (size_t)s * BH; koff = ks * KSL; }
                else        { Bh = g_hhi;                  Bl = g_hlo;                  koff = (ks - 2) * KSL; }
            } else {
                if (ks < 2) { Bh = g_hhi;      Bl = g_hlo;      koff = ks * KSL; }
                else        { Bh = g_hhi + BH; Bl = g_hlo + BH; koff = (ks - 2) * KSL; }
            }
            const __nv_bfloat16* BhP = Bh + (size_t)(koff + irow32) * 64 + ic8;
            const __nv_bfloat16* BlP = Bl + (size_t)(koff + irow32) * 64 + ic8;

            float acc[2][4][4];
#pragma unroll
            for (int i = 0; i < 2; i++)
#pragma unroll
                for (int j = 0; j < 4; j++)
#pragma unroll
                    for (int r = 0; r < 4; r++) acc[i][j][r] = 0.0f;

            // issue chunk 0
            {
                const uint32_t st = sbase;
#pragma unroll
                for (int it = 0; it < 4; it++) {
                    cpa16(st + offW[it],         WhP + (size_t)it * 32 * KTOT);
                    cpa16(st + 16384 + offW[it], WoP + (size_t)it * 32 * KTOT);
                }
#pragma unroll
                for (int it = 0; it < 2; it++) {
                    cpa16(st + 32768 + offB[it], BhP + (size_t)it * 32 * 64);
                    cpa16(st + 40960 + offB[it], BlP + (size_t)it * 32 * 64);
                }
                cpa_commit();
            }

            for (int ch = 0; ch < NCHK; ch++) {
                if (ch < NCHK - 1) {     // issue chunk ch+1 into other stage
                    const uint32_t st = sbase + ((ch + 1) & 1) * STGB;
                    const int kc = (ch + 1) * CHK;
#pragma unroll
                    for (int it = 0; it < 4; it++) {
                        cpa16(st + offW[it],         WhP + kc + (size_t)it * 32 * KTOT);
                        cpa16(st + 16384 + offW[it], WoP + kc + (size_t)it * 32 * KTOT);
                    }
#pragma unroll
                    for (int it = 0; it < 2; it++) {
                        cpa16(st + 32768 + offB[it], BhP + (size_t)kc * 64 + (size_t)it * 32 * 64);
                        cpa16(st + 40960 + offB[it], BlP + (size_t)kc * 64 + (size_t)it * 32 * 64);
                    }
                    cpa_commit();
                    cpa_wait1();
                } else {
                    cpa_wait0();
                }
                __syncthreads();

                // ---- compute chunk ch (all 4 kk) ----
                const uint32_t st = sbase + (ch & 1) * STGB;
#pragma unroll
                for (int kk = 0; kk < 4; kk++) {
                    const uint32_t aoff = (colq + kk * 32) ^ xorA;
                    uint32_t ahi0[4], ahi1[4], alo0[4], alo1[4];
                    ldsm4(st + baseA + aoff, ahi0);
                    ldsm4(st + baseA + 2048 + aoff, ahi1);
                    ldsm4(st + 16384 + baseA + aoff, alo0);
                    ldsm4(st + 16384 + baseA + 2048 + aoff, alo1);
#pragma unroll
                    for (int pl = 0; pl < 2; pl++) {
                        const int p = nh * 2 + pl;
                        const uint32_t boff = baseB + (uint32_t)kk * 2048
                                            + ((colq + p * 32) ^ xorB);
                        uint32_t bh[4], bl[4];
                        ldsm4t(st + 32768 + boff, bh);
                        ldsm4t(st + 40960 + boff, bl);
                        mma16816(acc[0][2 * pl],     ahi0, bh[0], bh[1]);
                        mma16816(acc[0][2 * pl],     ahi0, bl[0], bl[1]);
                        mma16816(acc[0][2 * pl],     alo0, bh[0], bh[1]);
                        mma16816(acc[0][2 * pl + 1], ahi0, bh[2], bh[3]);
                        mma16816(acc[0][2 * pl + 1], ahi0, bl[2], bl[3]);
                        mma16816(acc[0][2 * pl + 1], alo0, bh[2], bh[3]);
                        mma16816(acc[1][2 * pl],     ahi1, bh[0], bh[1]);
                        mma16816(acc[1][2 * pl],     ahi1, bl[0], bl[1]);
                        mma16816(acc[1][2 * pl],     alo1, bh[0], bh[1]);
                        mma16816(acc[1][2 * pl + 1], ahi1, bh[2], bh[3]);
                        mma16816(acc[1][2 * pl + 1], ahi1, bl[2], bl[3]);
                        mma16816(acc[1][2 * pl + 1], alo1, bh[2], bh[3]);
                    }
                }
                __syncthreads();
            }

            // ---- epilogue: acc -> split-K partials (direct, no reduce) ----
            {
                const int g4 = lane >> 2;
                const int tt = lane & 3;
#pragma unroll
                for (int i = 0; i < 2; i++) {
#pragma unroll
                    for (int j = 0; j < 4; j++) {
                        const int prow = m0 + mq * 32 + i * 16 + g4;
                        const int col  = nh * 32 + j * 8 + 2 * tt;
                        float* pp = g_partial + ((size_t)pgrp * NOUT + prow) * 64 + col;
                        *reinterpret_cast<float2*>(pp) =
                            make_float2(acc[i][j][0], acc[i][j][1]);
                        *reinterpret_cast<float2*>(pp + 8 * 64) =
                            make_float2(acc[i][j][2], acc[i][j][3]);
                    }
                }
            }
        }
        grid_barrier();

        // ---- cell phase: layer ccl, 8 units x 64 batches per CTA ----
        if (ccl == 0 ? do_l0 : do_l1) {
#pragma unroll
            for (int half = 0; half < 2; half++) {
                const int item = tid + half * NTHR;   // 0..511
                const int ul = item >> 6;             // 0..7
                const int b  = item & 63;
                const int u  = u0 + ul;
                float gv[4];
#pragma unroll
                for (int gate = 0; gate < 4; gate++) {
                    const int p = 4 * u + gate;
                    float sum = bias[(size_t)ccl * NOUT + gate * 1024 + u];
#pragma unroll
                    for (int ksi = 0; ksi < 4; ksi++)
                        sum += g_partial[((size_t)(ccl * 4 + ksi) * NOUT + p) * 64 + b];
                    gv[gate] = sum;
                }
                const size_t cidx = (size_t)ccl * BH + (size_t)u * 64 + b;
                const float gi = sigmoidf_(gv[0]);
                const float gj = tanhf(gv[1]);
                const float gf = sigmoidf_(gv[2]);
                const float go = sigmoidf_(gv[3]);
                const float cn = g_c[cidx] * gf + gi * gj;
                g_c[cidx] = cn;
                const float hn = tanhf(cn) * go;
                g_hf[cidx] = hn;
                __nv_bfloat16 hv, lv;
                split1(hn, hv, lv);
                g_hhi[cidx] = hv;
                g_hlo[cidx] = lv;
                if (ccl == 1) s_hn[ul][b] = hn;
            }
            if (ccl == 1) {
                __syncthreads();
                if (tid < 64) {
                    const int b2 = tid;
                    float* op = out + (size_t)(s - 1) * BH + (size_t)b2 * HID + u0;
                    reinterpret_cast<float4*>(op)[0] =
                        make_float4(s_hn[0][b2], s_hn[1][b2], s_hn[2][b2], s_hn[3][b2]);
                    reinterpret_cast<float4*>(op)[1] =
                        make_float4(s_hn[4][b2], s_hn[5][b2], s_hn[6][b2], s_hn[7][b2]);
                }
            }
        }
        grid_barrier();
    }

    // ======== tail: last_hidden + last_cell, de-transpose ========
    for (int i = gid; i < 2 * BH; i += GTH) {
        int l = i >> 16, rr = i & 65535, b = rr >> 10, u = rr & 1023;
        out[(size_t)SEQ * BH + i] = g_hf[(size_t)l * BH + (size_t)u * 64 + b];
        out[(size_t)SEQ * BH + 2 * BH + i] = g_c[(size_t)l * BH + (size_t)u * 64 + b];
    }
}

// ---------------- launch: ONE graph node ----------------
extern "C" void kernel_launch(void* const* d_in, const int* in_sizes, int n_in,
                              void* d_out, int out_size) {
    const float* input = (const float*)d_in[0];
    const float* h0    = (const float*)d_in[1];
    const float* c0    = (const float*)d_in[2];
    const float* W     = (const float*)d_in[3];
    const float* bias  = (const float*)d_in[4];
    float* out = (float*)d_out;

    cudaFuncSetAttribute(lstm_hmma, cudaFuncAttributeMaxDynamicSharedMemorySize, DSMEM);
    lstm_hmma<<<NBLK, NTHR, DSMEM>>>(input, h0, c0, W, bias, out);
}

// round 15
// speedup vs baseline: 1.0137x; 1.0137x over previous
#include <cuda_runtime.h>
#include <cuda_bf16.h>
#include <cstdint>

// BasicLSTM via mma.sync (HMMA bf16, 3-term fp32-split emulation).
// SEQ=512, BATCH=64, HID=1024, LAYERS=2.
// R15 = R14 with BALANCED 2 CTAs/SM: grid = 296 = 2*148 (placement LUT gives
// every SM exactly two CTAs -> two independent ldsm/HMMA streams per SM).
// 256 worker CTAs: lay(2) x M-tile(32) x split-K(4, K=512, 8 chunks).

#define SEQ    512
#define BATCH  64
#define HID    1024
#define KTOT   2048
#define NOUT   4096
#define BH     (BATCH * HID)        // 65536
#define NBLK   296                  // 2 per SM on 148 SMs
#define NWORK  256                  // worker CTAs
#define NTHR   256
#define GTH    (NBLK * NTHR)
#define KSL    512                  // K per slice (4 slices per layer)
#define CHK    64                   // K per chunk
#define NCHK   (KSL / CHK)          // 8
#define STGB   49152                // Ahi16K | Alo16K | Bhi8K | Blo8K
#define NSTG   2
#define DSMEM  (NSTG * STGB)        // 98304

// ---------------- device globals (no allocs) ----------------
__device__ __align__(128) __nv_bfloat16 g_xhi[(size_t)SEQ * HID * 64];
__device__ __align__(128) __nv_bfloat16 g_xlo[(size_t)SEQ * HID * 64];
__device__ __align__(128) __nv_bfloat16 g_wthi[(size_t)2 * NOUT * KTOT]; // [l][p][k]
__device__ __align__(128) __nv_bfloat16 g_wtlo[(size_t)2 * NOUT * KTOT];
__device__ __align__(128) __nv_bfloat16 g_hhi[2 * BH];    // [l][u][b]
__device__ __align__(128) __nv_bfloat16 g_hlo[2 * BH];
__device__ __align__(128) float g_partial[(size_t)8 * NOUT * 64]; // [lay*4+ks][p][b]
__device__ __align__(128) float g_c[2 * BH];              // [l][u][b]
__device__ __align__(128) float g_hf[2 * BH];             // [l][u][b]
__device__ unsigned g_bar_arrive;
__device__ unsigned g_bar_gen;

// ---------------- PTX helpers ----------------
__device__ __forceinline__ uint32_t smem_u32(const void* p) {
    uint32_t a;
    asm("{ .reg .u64 t; cvta.to.shared.u64 t, %1; cvt.u32.u64 %0, t; }"
        : "=r"(a) : "l"(p));
    return a;
}
__device__ __forceinline__ void cpa16(uint32_t s, const void* g) {
    asm volatile("cp.async.cg.shared.global [%0], [%1], 16;" :: "r"(s), "l"(g));
}
__device__ __forceinline__ void cpa_commit() {
    asm volatile("cp.async.commit_group;" ::: "memory");
}
__device__ __forceinline__ void cpa_wait1() {
    asm volatile("cp.async.wait_group 1;" ::: "memory");
}
__device__ __forceinline__ void cpa_wait0() {
    asm volatile("cp.async.wait_group 0;" ::: "memory");
}
__device__ __forceinline__ void ldsm4(uint32_t a, uint32_t* r) {
    asm volatile("ldmatrix.sync.aligned.m8n8.x4.shared.b16 {%0,%1,%2,%3}, [%4];"
                 : "=r"(r[0]), "=r"(r[1]), "=r"(r[2]), "=r"(r[3]) : "r"(a));
}
__device__ __forceinline__ void ldsm4t(uint32_t a, uint32_t* r) {
    asm volatile("ldmatrix.sync.aligned.m8n8.x4.trans.shared.b16 {%0,%1,%2,%3}, [%4];"
                 : "=r"(r[0]), "=r"(r[1]), "=r"(r[2]), "=r"(r[3]) : "r"(a));
}
__device__ __forceinline__ void mma16816(float* c, const uint32_t* a,
                                         uint32_t b0, uint32_t b1) {
    asm volatile("mma.sync.aligned.m16n8k16.row.col.f32.bf16.bf16.f32 "
                 "{%0,%1,%2,%3}, {%4,%5,%6,%7}, {%8,%9}, {%0,%1,%2,%3};"
                 : "+f"(c[0]), "+f"(c[1]), "+f"(c[2]), "+f"(c[3])
                 : "r"(a[0]), "r"(a[1]), "r"(a[2]), "r"(a[3]), "r"(b0), "r"(b1));
}
__device__ __forceinline__ float sigmoidf_(float x) { return 1.0f / (1.0f + expf(-x)); }
__device__ __forceinline__ void split1(float v, __nv_bfloat16& h, __nv_bfloat16& l) {
    h = __float2bfloat16_rn(v);
    l = __float2bfloat16_rn(v - __bfloat162float(h));
}
__device__ __forceinline__ uint32_t swz(uint32_t off) {
    return off ^ ((off >> 3) & 0x70);
}

// ---------------- grid barrier (all 296 blocks resident: 2/SM) -----------
__device__ __forceinline__ void grid_barrier() {
    __syncthreads();
    if (threadIdx.x == 0) {
        __threadfence();
        unsigned gen = *((volatile unsigned*)&g_bar_gen);
        if (atomicAdd(&g_bar_arrive, 1u) == NBLK - 1) {
            g_bar_arrive = 0;
            __threadfence();
            atomicAdd(&g_bar_gen, 1u);
        } else {
            while (*((volatile unsigned*)&g_bar_gen) == gen) { __nanosleep(20); }
        }
        __threadfence();
    }
    __syncthreads();
}

// ---------------- persistent kernel ----------------
__global__ void __launch_bounds__(NTHR, 2)
lstm_hmma(const float* __restrict__ input,   // [512,64,1024]
          const float* __restrict__ h0,      // [2,64,1024]
          const float* __restrict__ c0,      // [2,64,1024]
          const float* __restrict__ W,       // [2,2048,4096]
          const float* __restrict__ bias,    // [2,4096]
          float* __restrict__ out)
{
    extern __shared__ __align__(1024) char dsm[];
    const uint32_t sbase = smem_u32(dsm);

    __shared__ float s_tr[32][33];
    __shared__ float s_hn[8][64];

    const int tid  = threadIdx.x;
    const int wid  = tid >> 5;
    const int lane = tid & 31;
    const int bid  = blockIdx.x;
    const int gid  = bid * NTHR + tid;
    const bool worker = (bid < NWORK);
    const int lay  = (bid >> 7) & 1;  // 0: layer0@s, 1: layer1@(s-1)
    const int cg   = (bid >> 2) & 31; // M tile: rows [cg*128, +128)
    const int ks   = bid & 3;         // K slice: [ks*512, +512)
    const int pgrp = lay * 4 + ks;    // partial group
    const int m0   = cg * 128;
    // cell ownership (workers only): layer cl = bid&1, units [(bid>>1)*8, +8)
    const int ccl  = bid & 1;
    const int u0   = (bid >> 1) * 8;

    // warp mapping: 8 warps -> 4 mq x 2 nh m32n32 positions, all 4 kk each
    const int mq = wid >> 1;          // m offset mq*32
    const int nh = wid & 1;           // n offset nh*32

    // ======== phase 0a: x transpose [t][b][u] -> [t][u][b] + bf16 split ====
    for (int tile = bid; tile < SEQ * 64; tile += NBLK) {
        const int t  = tile >> 6;
        const int ut = (tile >> 1) & 31;
        const int bt = tile & 1;
        const int ub = ut * 32, bb = bt * 32;
#pragma unroll
        for (int it = 0; it < 4; it++) {
            int r = (tid >> 5) + it * 8, c = lane;
            s_tr[r][c] = input[((size_t)t * 64 + bb + r) * HID + ub + c];
        }
        __syncthreads();
#pragma unroll
        for (int it = 0; it < 4; it++) {
            int i = (tid >> 5) + it * 8, j = lane;
            __nv_bfloat16 hv, lv;
            split1(s_tr[j][i], hv, lv);
            size_t dst = ((size_t)t * HID + ub + i) * 64 + bb + j;
            g_xhi[dst] = hv;
            g_xlo[dst] = lv;
        }
        __syncthreads();
    }
    // ======== phase 0b: W transpose + gate-permute + split ========
    for (int tile = bid; tile < 2 * 64 * 128; tile += NBLK) {
        const int l  = tile >> 13;
        const int kt = (tile & 8191) >> 7;
        const int nt = tile & 127;
        const int k0 = kt * 32, n0 = nt * 32;
#pragma unroll
        for (int r = 0; r < 4; r++) {
            int kk = (tid >> 5) + r * 8;
            s_tr[kk][lane] = W[((size_t)l * KTOT + k0 + kk) * NOUT + n0 + lane];
        }
        __syncthreads();
#pragma unroll
        for (int r = 0; r < 4; r++) {
            int j = (tid >> 5) + r * 8;
            int n = n0 + j;
            int p = ((n & 1023) << 2) | (n >> 10);
            __nv_bfloat16 hv, lv;
            split1(s_tr[lane][j], hv, lv);
            size_t dst = ((size_t)l * NOUT + p) * KTOT + k0 + lane;
            g_wthi[dst] = hv;
            g_wtlo[dst] = lv;
        }
        __syncthreads();
    }
    // ======== phase 0c: seed h (transposed, split) and c (transposed) =====
    for (int tile = bid; tile < 256; tile += NBLK) {
        const int kind = tile >> 7;
        const int rest = tile & 127;
        const int l  = rest >> 6;
        const int ut = (rest >> 1) & 31;
        const int bt = rest & 1;
        const int ub = ut * 32, bb = bt * 32;
        const float* src = (kind == 0) ? h0 : c0;
#pragma unroll
        for (int it = 0; it < 4; it++) {
            int r = (tid >> 5) + it * 8, c = lane;
            s_tr[r][c] = src[((size_t)l * 64 + bb + r) * HID + ub + c];
        }
        __syncthreads();
#pragma unroll
        for (int it = 0; it < 4; it++) {
            int i = (tid >> 5) + it * 8, j = lane;
            float v = s_tr[j][i];
            if (kind == 0) {
                __nv_bfloat16 hv, lv;
                split1(v, hv, lv);
                size_t dst = (size_t)l * BH + (size_t)(ub + i) * 64 + bb + j;
                g_hhi[dst] = hv;
                g_hlo[dst] = lv;
            } else {
                g_c[(size_t)l * BH + (size_t)(ub + i) * 64 + bb + j] = v;
            }
        }
        __syncthreads();
    }
    grid_barrier();

    // ---- lane-constant ldmatrix row bases + swizzle XORs ----
    const int q  = lane >> 3, r8 = lane & 7;
    const int rowA = mq * 32 + r8 + (q & 1) * 8;
    const uint32_t baseA = (uint32_t)rowA * 128;
    const uint32_t xorA  = (uint32_t)(rowA & 7) * 16;
    const int rowB = (q & 1) * 8 + r8;
    const uint32_t baseB = (uint32_t)rowB * 128;
    const uint32_t xorB  = (uint32_t)(rowB & 7) * 16;
    const uint32_t colq  = (uint32_t)(q >> 1) * 16;

    // ---- hoisted cp.async addressing ----
    const int irow32 = tid >> 3;               // 0..31
    const int ic8    = (tid & 7) * 8;
    uint32_t offW[4], offB[2];
#pragma unroll
    for (int it = 0; it < 4; it++)
        offW[it] = swz((uint32_t)(irow32 + it * 32) * 128 + (tid & 7) * 16);
#pragma unroll
    for (int it = 0; it < 2; it++)
        offB[it] = swz((uint32_t)(irow32 + it * 32) * 128 + (tid & 7) * 16);

    // W per-thread base pointers (row block it adds 32*KTOT)
    const __nv_bfloat16* WhP = g_wthi + ((size_t)lay * NOUT + m0 + irow32) * KTOT
                             + ks * KSL + ic8;
    const __nv_bfloat16* WoP = g_wtlo + ((size_t)lay * NOUT + m0 + irow32) * KTOT
                             + ks * KSL + ic8;

    // ======== main recurrence: 513 super-steps ========
    for (int s = 0; s <= SEQ; s++) {
        const bool do_l0 = (s < SEQ);
        const bool do_l1 = (s >= 1);
        const bool active = worker && ((lay == 0) ? do_l0 : do_l1);

        if (active) {
            // ---- B operand selection ----
            const __nv_bfloat16 *Bh, *Bl;
            int koff;
            if (lay == 0) {
                if (ks < 2) { Bh = g_xhi + (size_t)s * BH; Bl = g_xlo + (size_t)s * BH; koff = ks * KSL; }
                else        { Bh = g_hhi;                  Bl = g_hlo;                  koff = (ks - 2) * KSL; }
            } else {
                if (ks < 2) { Bh = g_hhi;      Bl = g_hlo;      koff = ks * KSL; }
                else        { Bh = g_hhi + BH; Bl = g_hlo + BH; koff = (ks - 2) * KSL; }
            }
            const __nv_bfloat16* BhP = Bh + (size_t)(koff + irow32) * 64 + ic8;
            const __nv_bfloat16* BlP = Bl + (size_t)(koff + irow32) * 64 + ic8;

            float acc[2][4][4];
#pragma unroll
            for (int i = 0; i < 2; i++)
#pragma unroll
                for (int j = 0; j < 4; j++)
#pragma unroll
                    for (int r = 0; r < 4; r++) acc[i][j][r] = 0.0f;

            // issue chunk 0
            {
                const uint32_t st = sbase;
#pragma unroll
                for (int it = 0; it < 4; it++) {
                    cpa16(st + offW[it],         WhP + (size_t)it * 32 * KTOT);
                    cpa16(st + 16384 + offW[it], WoP + (size_t)it * 32 * KTOT);
                }
#pragma unroll
                for (int it = 0; it < 2; it++) {
                    cpa16(st + 32768 + offB[it], BhP + (size_t)it * 32 * 64);
                    cpa16(st + 40960 + offB[it], BlP + (size_t)it * 32 * 64);
                }
                cpa_commit();
            }

            for (int ch = 0; ch < NCHK; ch++) {
                if (ch < NCHK - 1) {     // issue chunk ch+1 into other stage
                    const uint32_t st = sbase + ((ch + 1) & 1) * STGB;
                    const int kc = (ch + 1) * CHK;
#pragma unroll
                    for (int it = 0; it < 4; it++) {
                        cpa16(st + offW[it],         WhP + kc + (size_t)it * 32 * KTOT);
                        cpa16(st + 16384 + offW[it], WoP + kc + (size_t)it * 32 * KTOT);
                    }
#pragma unroll
                    for (int it = 0; it < 2; it++) {
                        cpa16(st + 32768 + offB[it], BhP + (size_t)kc * 64 + (size_t)it * 32 * 64);
                        cpa16(st + 40960 + offB[it], BlP + (size_t)kc * 64 + (size_t)it * 32 * 64);
                    }
                    cpa_commit();
                    cpa_wait1();
                } else {
                    cpa_wait0();
                }
                __syncthreads();

                // ---- compute chunk ch (all 4 kk) ----
                const uint32_t st = sbase + (ch & 1) * STGB;
#pragma unroll
                for (int kk = 0; kk < 4; kk++) {
                    const uint32_t aoff = (colq + kk * 32) ^ xorA;
                    uint32_t ahi0[4], ahi1[4], alo0[4], alo1[4];
                    ldsm4(st + baseA + aoff, ahi0);
                    ldsm4(st + baseA + 2048 + aoff, ahi1);
                    ldsm4(st + 16384 + baseA + aoff, alo0);
                    ldsm4(st + 16384 + baseA + 2048 + aoff, alo1);
#pragma unroll
                    for (int pl = 0; pl < 2; pl++) {
                        const int p = nh * 2 + pl;
                        const uint32_t boff = baseB + (uint32_t)kk * 2048
                                            + ((colq + p * 32) ^ xorB);
                        uint32_t bh[4], bl[4];
                        ldsm4t(st + 32768 + boff, bh);
                        ldsm4t(st + 40960 + boff, bl);
                        mma16816(acc[0][2 * pl],     ahi0, bh[0], bh[1]);
                        mma16816(acc[0][2 * pl],     ahi0, bl[0], bl[1]);
                        mma16816(acc[0][2 * pl],     alo0, bh[0], bh[1]);
                        mma16816(acc[0][2 * pl + 1], ahi0, bh[2], bh[3]);
                        mma16816(acc[0][2 * pl + 1], ahi0, bl[2], bl[3]);
                        mma16816(acc[0][2 * pl + 1], alo0, bh[2], bh[3]);
                        mma16816(acc[1][2 * pl],     ahi1, bh[0], bh[1]);
                        mma16816(acc[1][2 * pl],     ahi1, bl[0], bl[1]);
                        mma16816(acc[1][2 * pl],     alo1, bh[0], bh[1]);
                        mma16816(acc[1][2 * pl + 1], ahi1, bh[2], bh[3]);
                        mma16816(acc[1][2 * pl + 1], ahi1, bl[2], bl[3]);
                        mma16816(acc[1][2 * pl + 1], alo1, bh[2], bh[3]);
                    }
                }
                __syncthreads();
            }

            // ---- epilogue: acc -> split-K partials (direct, no reduce) ----
            {
                const int g4 = lane >> 2;
                const int tt = lane & 3;
#pragma unroll
                for (int i = 0; i < 2; i++) {
#pragma unroll
                    for (int j = 0; j < 4; j++) {
                        const int prow = m0 + mq * 32 + i * 16 + g4;
                        const int col  = nh * 32 + j * 8 + 2 * tt;
                        float* pp = g_partial + ((size_t)pgrp * NOUT + prow) * 64 + col;
                        *reinterpret_cast<float2*>(pp) =
                            make_float2(acc[i][j][0], acc[i][j][1]);
                        *reinterpret_cast<float2*>(pp + 8 * 64) =
                            make_float2(acc[i][j][2], acc[i][j][3]);
                    }
                }
            }
        }
        grid_barrier();

        // ---- cell phase: layer ccl, 8 units x 64 batches per worker CTA ----
        if (worker && (ccl == 0 ? do_l0 : do_l1)) {
#pragma unroll
            for (int half = 0; half < 2; half++) {
                const int item = tid + half * NTHR;   // 0..511
                const int ul = item >> 6;             // 0..7
                const int b  = item & 63;
                const int u  = u0 + ul;
                float gv[4];
#pragma unroll
                for (int gate = 0; gate < 4; gate++) {
                    const int p = 4 * u + gate;
                    float sum = bias[(size_t)ccl * NOUT + gate * 1024 + u];
#pragma unroll
                    for (int ksi = 0; ksi < 4; ksi++)
                        sum += g_partial[((size_t)(ccl * 4 + ksi) * NOUT + p) * 64 + b];
                    gv[gate] = sum;
                }
                const size_t cidx = (size_t)ccl * BH + (size_t)u * 64 + b;
                const float gi = sigmoidf_(gv[0]);
                const float gj = tanhf(gv[1]);
                const float gf = sigmoidf_(gv[2]);
                const float go = sigmoidf_(gv[3]);
                const float cn = g_c[cidx] * gf + gi * gj;
                g_c[cidx] = cn;
                const float hn = tanhf(cn) * go;
                g_hf[cidx] = hn;
                __nv_bfloat16 hv, lv;
                split1(hn, hv, lv);
                g_hhi[cidx] = hv;
                g_hlo[cidx] = lv;
                if (ccl == 1) s_hn[ul][b] = hn;
            }
            if (ccl == 1) {
                __syncthreads();
                if (tid < 64) {
                    const int b2 = tid;
                    float* op = out + (size_t)(s - 1) * BH + (size_t)b2 * HID + u0;
                    reinterpret_cast<float4*>(op)[0] =
                        make_float4(s_hn[0][b2], s_hn[1][b2], s_hn[2][b2], s_hn[3][b2]);
                    reinterpret_cast<float4*>(op)[1] =
                        make_float4(s_hn[4][b2], s_hn[5][b2], s_hn[6][b2], s_hn[7][b2]);
                }
            }
        }
        grid_barrier();
    }

    // ======== tail: last_hidden + last_cell, de-transpose ========
    for (int i = gid; i < 2 * BH; i += GTH) {
        int l = i >> 16, rr = i & 65535, b = rr >> 10, u = rr & 1023;
        out[(size_t)SEQ * BH + i] = g_hf[(size_t)l * BH + (size_t)u * 64 + b];
        out[(size_t)SEQ * BH + 2 * BH + i] = g_c[(size_t)l * BH + (size_t)u * 64 + b];
    }
}

// ---------------- launch: ONE graph node ----------------
extern "C" void kernel_launch(void* const* d_in, const int* in_sizes, int n_in,
                              void* d_out, int out_size) {
    const float* input = (const float*)d_in[0];
    const float* h0    = (const float*)d_in[1];
    const float* c0    = (const float*)d_in[2];
    const float* W     = (const float*)d_in[3];
    const float* bias  = (const float*)d_in[4];
    float* out = (float*)d_out;

    cudaFuncSetAttribute(lstm_hmma, cudaFuncAttributeMaxDynamicSharedMemorySize, DSMEM);
    lstm_hmma<<<NBLK, NTHR, DSMEM>>>(input, h0, c0, W, bias, out);
}